// round 2
// baseline (speedup 1.0000x reference)
#include <cuda_runtime.h>

// ---------------------------------------------------------------------------
// Problem constants
// ---------------------------------------------------------------------------
#define BATCH 2
#define SEQ   2048
#define DMODEL 4096
#define NHEADS 32
#define NKV    8
#define HEADD  128
#define GRP    4
#define PAST   1024
#define TTOT   3072
#define NTOK   (BATCH * SEQ)   // 4096

// ---------------------------------------------------------------------------
// Scratch buffers (device globals: no cudaMalloc allowed)
// ---------------------------------------------------------------------------
__device__ float g_q[(size_t)NTOK * DMODEL];            // [B,S,H,HD]  64 MB
__device__ float g_kn[(size_t)NTOK * NKV * HEADD];      // [B,S,KV,HD] 16 MB
__device__ float g_vn[(size_t)NTOK * NKV * HEADD];      // 16 MB
__device__ float g_att[(size_t)NTOK * DMODEL];          // [B,S,H,HD]  64 MB

// ---------------------------------------------------------------------------
// fp32 SGEMM: C[M,N] = A[M,K] * W[K,N], all row-major.
// 128x128 block tile, BK=8, 256 threads, 8x8 per-thread register tile.
// ---------------------------------------------------------------------------
__global__ __launch_bounds__(256, 2) void sgemm_kernel(
    const float* __restrict__ A, const float* __restrict__ W,
    float* __restrict__ C, int M, int N, int K)
{
    __shared__ float As[8][128];   // transposed A tile: As[k][m]
    __shared__ float Bs[8][128];   // Bs[k][n]

    const int tid  = threadIdx.x;
    const int row0 = blockIdx.y * 128;
    const int col0 = blockIdx.x * 128;

    const int arow = tid >> 1;          // 0..127
    const int ac   = (tid & 1) * 4;     // 0 or 4
    const int brow = tid >> 5;          // 0..7
    const int bc   = (tid & 31) * 4;    // 0..124

    const int tx = tid & 15;            // col group
    const int ty = tid >> 4;            // row group

    float acc[8][8];
#pragma unroll
    for (int i = 0; i < 8; i++)
#pragma unroll
        for (int j = 0; j < 8; j++) acc[i][j] = 0.f;

    const float* Ap = A + (size_t)(row0 + arow) * K + ac;
    const float* Wp = W + (size_t)brow * N + col0 + bc;

    for (int k0 = 0; k0 < K; k0 += 8) {
        float4 av = *(const float4*)(Ap + k0);
        float4 wv = *(const float4*)(Wp + (size_t)k0 * N);
        __syncthreads();
        As[ac + 0][arow] = av.x;
        As[ac + 1][arow] = av.y;
        As[ac + 2][arow] = av.z;
        As[ac + 3][arow] = av.w;
        *(float4*)&Bs[brow][bc] = wv;
        __syncthreads();
#pragma unroll
        for (int kk = 0; kk < 8; kk++) {
            float a[8], b[8];
            *(float4*)(a)     = *(const float4*)&As[kk][ty * 8];
            *(float4*)(a + 4) = *(const float4*)&As[kk][ty * 8 + 4];
            *(float4*)(b)     = *(const float4*)&Bs[kk][tx * 8];
            *(float4*)(b + 4) = *(const float4*)&Bs[kk][tx * 8 + 4];
#pragma unroll
            for (int i = 0; i < 8; i++)
#pragma unroll
                for (int j = 0; j < 8; j++)
                    acc[i][j] = fmaf(a[i], b[j], acc[i][j]);
        }
    }

#pragma unroll
    for (int i = 0; i < 8; i++) {
        float* cp = C + (size_t)(row0 + ty * 8 + i) * N + col0 + tx * 8;
        float4 o0 = make_float4(acc[i][0], acc[i][1], acc[i][2], acc[i][3]);
        float4 o1 = make_float4(acc[i][4], acc[i][5], acc[i][6], acc[i][7]);
        *(float4*)cp       = o0;
        *(float4*)(cp + 4) = o1;
    }
}

// ---------------------------------------------------------------------------
// fp32 flash attention with KV-cache (no concat copy: branch past vs new).
// BM=64 queries, BN=128 keys per tile, HD=128. 256 threads.
// ---------------------------------------------------------------------------
#define ATT_BM 64
#define ATT_BN 128
#define PADW   132   // padded row stride (floats) -> conflict-free, float4 aligned

#define ATT_SMEM_FLOATS (ATT_BM*PADW /*Qs*/ + 128*PADW /*Kt*/ + 128*PADW /*Vs*/ \
                         + ATT_BM*PADW /*Ss*/ + 3*ATT_BM /*m,l,alpha*/)
#define ATT_SMEM_BYTES  (ATT_SMEM_FLOATS * sizeof(float))   // 203,520 B

__global__ __launch_bounds__(256, 1) void attn_kernel(
    const float* __restrict__ past_k, const float* __restrict__ past_v)
{
    extern __shared__ float sm[];
    float* Qs   = sm;                      // [64][PADW]   Qs[m][d]
    float* Kt   = Qs + ATT_BM * PADW;      // [128][PADW]  Kt[d][n]
    float* Vs   = Kt + 128 * PADW;         // [128][PADW]  Vs[n][d]
    float* Ss   = Vs + 128 * PADW;         // [64][PADW]   scores / probs
    float* mrow = Ss + ATT_BM * PADW;      // [64]
    float* lrow = mrow + ATT_BM;           // [64]
    float* arow = lrow + ATT_BM;           // [64] alpha rescale

    const int tid = threadIdx.x;
    const int q0  = blockIdx.x * ATT_BM;
    const int h   = blockIdx.y;
    const int b   = blockIdx.z;
    const int kvh = h >> 2;   // h / GRP

    if (tid < ATT_BM) { mrow[tid] = -1e30f; lrow[tid] = 0.f; }

    // ---- load Q tile [64][128] = 2048 float4 slots ----
    {
        const float* qb = g_q + (size_t)(b * SEQ + q0) * DMODEL + h * HEADD;
#pragma unroll
        for (int i = 0; i < 8; i++) {
            int idx = tid + i * 256;
            int qr = idx >> 5, qc = (idx & 31) << 2;
            *(float4*)&Qs[qr * PADW + qc] =
                *(const float4*)(qb + (size_t)qr * DMODEL + qc);
        }
    }

    const int tx = tid & 15;   // 0..15
    const int ty = tid >> 4;   // 0..15

    float acc[4][8];
#pragma unroll
    for (int i = 0; i < 4; i++)
#pragma unroll
        for (int j = 0; j < 8; j++) acc[i][j] = 0.f;

    const int kmax = PAST + q0 + ATT_BM;   // exclusive bound on key index

    for (int n0 = 0; n0 < kmax; n0 += ATT_BN) {
        __syncthreads();   // previous tile's readers done before overwriting smem

        // ---- load K tile (transposed) and V tile ----
        // 128 keys x 128 dims = 16384 floats = 4096 float4 slots -> 16 iters
#pragma unroll
        for (int i = 0; i < 16; i++) {
            int idx = tid + i * 256;          // 0..4095
            int kr = idx >> 5;                // key row within tile, 0..127
            int kc = (idx & 31) << 2;         // d offset, 0..124
            int j  = n0 + kr;                 // global key index (< TTOT always)
            const float *kp, *vp;
            if (j < PAST) {
                size_t off = ((size_t)(b * PAST + j) * NKV + kvh) * HEADD;
                kp = past_k + off;  vp = past_v + off;
            } else {
                size_t off = ((size_t)(b * SEQ + (j - PAST)) * NKV + kvh) * HEADD;
                kp = g_kn + off;    vp = g_vn + off;
            }
            float4 k4 = *(const float4*)(kp + kc);
            Kt[(kc + 0) * PADW + kr] = k4.x;
            Kt[(kc + 1) * PADW + kr] = k4.y;
            Kt[(kc + 2) * PADW + kr] = k4.z;
            Kt[(kc + 3) * PADW + kr] = k4.w;
            *(float4*)&Vs[kr * PADW + kc] = *(const float4*)(vp + kc);
        }
        __syncthreads();

        // ---- S = Q K^T * scale (+ causal mask) ----
        float sacc[4][8];
#pragma unroll
        for (int i = 0; i < 4; i++)
#pragma unroll
            for (int j = 0; j < 8; j++) sacc[i][j] = 0.f;

#pragma unroll 4
        for (int kk = 0; kk < HEADD; kk++) {
            float a[4];
#pragma unroll
            for (int i = 0; i < 4; i++) a[i] = Qs[(ty * 4 + i) * PADW + kk];
            float bb[8];
            *(float4*)(bb)     = *(const float4*)&Kt[kk * PADW + tx * 8];
            *(float4*)(bb + 4) = *(const float4*)&Kt[kk * PADW + tx * 8 + 4];
#pragma unroll
            for (int i = 0; i < 4; i++)
#pragma unroll
                for (int j = 0; j < 8; j++)
                    sacc[i][j] = fmaf(a[i], bb[j], sacc[i][j]);
        }

        const bool need_mask = (n0 + ATT_BN - 1 > PAST + q0);
        const float sc = 0.088388347648318447f;   // 1/sqrt(128)
#pragma unroll
        for (int i = 0; i < 4; i++) {
            int qrow = ty * 4 + i;
            int lim  = PAST + q0 + qrow;          // allowed: key <= lim
            float o[8];
#pragma unroll
            for (int j = 0; j < 8; j++) {
                float s = sacc[i][j] * sc;
                if (need_mask && (n0 + tx * 8 + j > lim)) s = -1e30f;
                o[j] = s;
            }
            *(float4*)&Ss[qrow * PADW + tx * 8]     = *(float4*)(o);
            *(float4*)&Ss[qrow * PADW + tx * 8 + 4] = *(float4*)(o + 4);
        }
        __syncthreads();

        // ---- online softmax (4 lanes per row) ----
        {
            int r  = tid >> 2;
            int qd = tid & 3;
            float* srow = Ss + r * PADW + qd * 32;
            float lm = -1e30f;
#pragma unroll
            for (int jj = 0; jj < 32; jj++) lm = fmaxf(lm, srow[jj]);
            lm = fmaxf(lm, __shfl_xor_sync(0xffffffffu, lm, 1));
            lm = fmaxf(lm, __shfl_xor_sync(0xffffffffu, lm, 2));
            float mprev = mrow[r];
            float mnew  = fmaxf(mprev, lm);
            float ls = 0.f;
#pragma unroll
            for (int jj = 0; jj < 32; jj++) {
                float p = __expf(srow[jj] - mnew);
                srow[jj] = p;
                ls += p;
            }
            ls += __shfl_xor_sync(0xffffffffu, ls, 1);
            ls += __shfl_xor_sync(0xffffffffu, ls, 2);
            if (qd == 0) {
                float al = __expf(mprev - mnew);
                mrow[r] = mnew;
                lrow[r] = lrow[r] * al + ls;
                arow[r] = al;
            }
        }
        __syncthreads();

        // ---- O = O*alpha + P V ----
#pragma unroll
        for (int i = 0; i < 4; i++) {
            float al = arow[ty * 4 + i];
#pragma unroll
            for (int j = 0; j < 8; j++) acc[i][j] *= al;
        }
#pragma unroll 4
        for (int j = 0; j < ATT_BN; j++) {
            float vv[8];
            *(float4*)(vv)     = *(const float4*)&Vs[j * PADW + tx * 8];
            *(float4*)(vv + 4) = *(const float4*)&Vs[j * PADW + tx * 8 + 4];
            float p0 = Ss[(ty * 4 + 0) * PADW + j];
            float p1 = Ss[(ty * 4 + 1) * PADW + j];
            float p2 = Ss[(ty * 4 + 2) * PADW + j];
            float p3 = Ss[(ty * 4 + 3) * PADW + j];
#pragma unroll
            for (int c = 0; c < 8; c++) {
                acc[0][c] = fmaf(p0, vv[c], acc[0][c]);
                acc[1][c] = fmaf(p1, vv[c], acc[1][c]);
                acc[2][c] = fmaf(p2, vv[c], acc[2][c]);
                acc[3][c] = fmaf(p3, vv[c], acc[3][c]);
            }
        }
    }

    // ---- epilogue: normalize and write attn output [B,S,H,HD] ----
#pragma unroll
    for (int i = 0; i < 4; i++) {
        int qrow = ty * 4 + i;
        float inv = 1.f / lrow[qrow];
        float* op = g_att + (size_t)(b * SEQ + q0 + qrow) * DMODEL + h * HEADD + tx * 8;
        float4 o0 = make_float4(acc[i][0] * inv, acc[i][1] * inv,
                                acc[i][2] * inv, acc[i][3] * inv);
        float4 o1 = make_float4(acc[i][4] * inv, acc[i][5] * inv,
                                acc[i][6] * inv, acc[i][7] * inv);
        *(float4*)op       = o0;
        *(float4*)(op + 4) = o1;
    }
}

// ---------------------------------------------------------------------------
// Launch
// ---------------------------------------------------------------------------
extern "C" void kernel_launch(void* const* d_in, const int* in_sizes, int n_in,
                              void* d_out, int out_size)
{
    const float* x      = (const float*)d_in[0];
    const float* past_k = (const float*)d_in[1];
    const float* past_v = (const float*)d_in[2];
    const float* Wq     = (const float*)d_in[3];
    const float* Wk     = (const float*)d_in[4];
    const float* Wv     = (const float*)d_in[5];
    const float* Wo     = (const float*)d_in[6];
    float* out = (float*)d_out;

    void *pq = nullptr, *pkn = nullptr, *pvn = nullptr, *patt = nullptr;
    cudaGetSymbolAddress(&pq,  g_q);
    cudaGetSymbolAddress(&pkn, g_kn);
    cudaGetSymbolAddress(&pvn, g_vn);
    cudaGetSymbolAddress(&patt, g_att);

    cudaFuncSetAttribute(attn_kernel,
                         cudaFuncAttributeMaxDynamicSharedMemorySize,
                         (int)ATT_SMEM_BYTES);

    dim3 blk(256);
    // QKV projections
    sgemm_kernel<<<dim3(DMODEL / 128, NTOK / 128), blk>>>(
        x, Wq, (float*)pq, NTOK, DMODEL, DMODEL);
    sgemm_kernel<<<dim3((NKV * HEADD) / 128, NTOK / 128), blk>>>(
        x, Wk, (float*)pkn, NTOK, NKV * HEADD, DMODEL);
    sgemm_kernel<<<dim3((NKV * HEADD) / 128, NTOK / 128), blk>>>(
        x, Wv, (float*)pvn, NTOK, NKV * HEADD, DMODEL);
    // flash attention with cache
    attn_kernel<<<dim3(SEQ / ATT_BM, NHEADS, BATCH), blk, ATT_SMEM_BYTES>>>(
        past_k, past_v);
    // output projection -> d_out
    sgemm_kernel<<<dim3(DMODEL / 128, NTOK / 128), blk>>>(
        (const float*)patt, Wo, out, NTOK, DMODEL, DMODEL);
}

// round 5
// speedup vs baseline: 1.5789x; 1.5789x over previous
#include <cuda_runtime.h>
#include <cuda_bf16.h>
#include <cstdint>

// ---------------------------------------------------------------------------
// Problem constants
// ---------------------------------------------------------------------------
#define BATCH 2
#define SEQ   2048
#define DMODEL 4096
#define NHEADS 32
#define NKV    8
#define HEADD  128
#define GRP    4
#define PAST   1024
#define TTOT   3072
#define NTOK   (BATCH * SEQ)   // 4096
#define KDIM   DMODEL          // inner dim of every projection (4096)

// ---------------------------------------------------------------------------
// Scratch buffers (device globals: no cudaMalloc allowed)
// ---------------------------------------------------------------------------
__device__ float g_q[(size_t)NTOK * DMODEL];            // 64 MB
__device__ float g_kn[(size_t)NTOK * NKV * HEADD];      // 16 MB
__device__ float g_vn[(size_t)NTOK * NKV * HEADD];      // 16 MB
__device__ float g_att[(size_t)NTOK * DMODEL];          // 64 MB

__device__ __nv_bfloat16 g_xhi[(size_t)NTOK * DMODEL];
__device__ __nv_bfloat16 g_xlo[(size_t)NTOK * DMODEL];
__device__ __nv_bfloat16 g_athi[(size_t)NTOK * DMODEL];
__device__ __nv_bfloat16 g_atlo[(size_t)NTOK * DMODEL];
__device__ __nv_bfloat16 g_wqt_hi[(size_t)DMODEL * KDIM];   // [N][K] transposed
__device__ __nv_bfloat16 g_wqt_lo[(size_t)DMODEL * KDIM];
__device__ __nv_bfloat16 g_wkt_hi[(size_t)(NKV*HEADD) * KDIM];
__device__ __nv_bfloat16 g_wkt_lo[(size_t)(NKV*HEADD) * KDIM];
__device__ __nv_bfloat16 g_wvt_hi[(size_t)(NKV*HEADD) * KDIM];
__device__ __nv_bfloat16 g_wvt_lo[(size_t)(NKV*HEADD) * KDIM];
__device__ __nv_bfloat16 g_wot_hi[(size_t)DMODEL * KDIM];
__device__ __nv_bfloat16 g_wot_lo[(size_t)DMODEL * KDIM];

// ---------------------------------------------------------------------------
// small PTX helpers (all baseline sm_80+ instructions; no tcgen05!)
// ---------------------------------------------------------------------------
__device__ __forceinline__ uint32_t smem_to_u32(const void* p) {
    uint32_t a;
    asm("{ .reg .u64 t; cvta.to.shared.u64 t, %1; cvt.u32.u64 %0, t; }"
        : "=r"(a) : "l"(p));
    return a;
}
#define CP_ASYNC16(dst, src) \
    asm volatile("cp.async.ca.shared.global [%0], [%1], 16;" \
        :: "r"(dst), "l"(src))
#define CP_COMMIT() asm volatile("cp.async.commit_group;")
#define CP_WAIT1()  asm volatile("cp.async.wait_group 1;")
#define CP_WAIT0()  asm volatile("cp.async.wait_group 0;")

#define LDMATRIX_X4(r0, r1, r2, r3, addr) \
    asm volatile("ldmatrix.sync.aligned.m8n8.x4.shared.b16 {%0,%1,%2,%3}, [%4];" \
        : "=r"(r0), "=r"(r1), "=r"(r2), "=r"(r3) : "r"(addr))

__device__ __forceinline__ void mma_bf16(float* c, const uint32_t* a,
                                         const uint32_t* b) {
    asm volatile(
        "mma.sync.aligned.m16n8k16.row.col.f32.bf16.bf16.f32 "
        "{%0,%1,%2,%3}, {%4,%5,%6,%7}, {%8,%9}, {%0,%1,%2,%3};"
        : "+f"(c[0]), "+f"(c[1]), "+f"(c[2]), "+f"(c[3])
        : "r"(a[0]), "r"(a[1]), "r"(a[2]), "r"(a[3]), "r"(b[0]), "r"(b[1]));
}

// ---------------------------------------------------------------------------
// fp32 -> bf16 hi/lo split (row-major preserved)
// ---------------------------------------------------------------------------
__global__ __launch_bounds__(256) void split_kernel(
    const float* __restrict__ src, __nv_bfloat16* __restrict__ hi,
    __nv_bfloat16* __restrict__ lo, size_t n)
{
    size_t i = ((size_t)blockIdx.x * 256 + threadIdx.x) * 4;
    if (i >= n) return;
    float4 v = *(const float4*)(src + i);
    float vs[4] = {v.x, v.y, v.z, v.w};
    __nv_bfloat16 h[4], l[4];
#pragma unroll
    for (int j = 0; j < 4; j++) {
        h[j] = __float2bfloat16(vs[j]);
        l[j] = __float2bfloat16(vs[j] - __bfloat162float(h[j]));
    }
    *(uint2*)(hi + i) = *(uint2*)h;
    *(uint2*)(lo + i) = *(uint2*)l;
}

// ---------------------------------------------------------------------------
// Transpose + split: W[K][N] fp32 -> Wt_hi/lo[N][K] bf16
// ---------------------------------------------------------------------------
__global__ __launch_bounds__(256) void tsplit_kernel(
    const float* __restrict__ W, __nv_bfloat16* __restrict__ thi,
    __nv_bfloat16* __restrict__ tlo, int Kd, int Nd)
{
    __shared__ float t[32][33];
    int tx = threadIdx.x & 31;
    int ty = threadIdx.x >> 5;          // 0..7
    int n_base = blockIdx.x * 32;
    int k_base = blockIdx.y * 32;
#pragma unroll
    for (int j = 0; j < 32; j += 8)
        t[ty + j][tx] = W[(size_t)(k_base + ty + j) * Nd + n_base + tx];
    __syncthreads();
#pragma unroll
    for (int j = 0; j < 32; j += 8) {
        int n = n_base + ty + j;
        int k = k_base + tx;
        float v = t[tx][ty + j];
        __nv_bfloat16 h = __float2bfloat16(v);
        thi[(size_t)n * Kd + k] = h;
        tlo[(size_t)n * Kd + k] = __float2bfloat16(v - __bfloat162float(h));
    }
}

// ---------------------------------------------------------------------------
// HMMA (mma.sync m16n8k16 bf16) split GEMM:
//   C[M, Ntot] = (Ahi+Alo)[M,K] x ((Bt_hi+Bt_lo)[Ntot,K])^T   (drops lo*lo)
// 128x128 CTA tile, BK=32, 256 threads (8 warps, 4x2), warp tile 32x64.
// cp.async double buffering. fp32 accumulation in registers.
// ---------------------------------------------------------------------------
#define BK       32
#define ASTRIDE  40                       // bf16 row stride (80 B) in smem
#define TILE_B   (128 * ASTRIDE * 2)      // 10,240 B per tile
#define STAGE_B  (4 * TILE_B)             // Ahi Alo Bhi Blo = 40,960 B
#define GSMEM_B  (2 * STAGE_B)            // 81,920 B
#define NCHUNK   (KDIM / BK)              // 128

__device__ __forceinline__ void gemm_load_stage(
    uint32_t smem_u, int stage, int kc, int tid,
    const __nv_bfloat16* const* srcs)
{
#pragma unroll
    for (int t = 0; t < 4; t++) {
        uint32_t dbase = smem_u + stage * STAGE_B + t * TILE_B;
        const __nv_bfloat16* sb = srcs[t] + kc * BK;
#pragma unroll
        for (int i = 0; i < 2; i++) {
            int slot = tid + i * 256;       // 0..511
            int r = slot >> 2;              // row 0..127
            int c = slot & 3;               // 16B unit (8 bf16)
            uint32_t dst = dbase + (uint32_t)(r * ASTRIDE + c * 8) * 2;
            CP_ASYNC16(dst, sb + (size_t)r * KDIM + c * 8);
        }
    }
    CP_COMMIT();
}

__global__ __launch_bounds__(256, 1) void hmma_gemm_kernel(
    const __nv_bfloat16* __restrict__ Ahi, const __nv_bfloat16* __restrict__ Alo,
    const __nv_bfloat16* __restrict__ Bhi, const __nv_bfloat16* __restrict__ Blo,
    float* __restrict__ C, int Ntot)
{
    extern __shared__ char smem[];
    const uint32_t smem_u = smem_to_u32(smem);
    const int tid  = threadIdx.x;
    const int lane = tid & 31;
    const int wid  = tid >> 5;
    const int wm   = (wid >> 1) * 32;      // warp M offset in CTA tile
    const int wn   = (wid & 1) * 64;       // warp N offset
    const int m0   = blockIdx.y * 128;
    const int n0   = blockIdx.x * 128;

    const __nv_bfloat16* srcs[4] = {
        Ahi + (size_t)m0 * KDIM, Alo + (size_t)m0 * KDIM,
        Bhi + (size_t)n0 * KDIM, Blo + (size_t)n0 * KDIM };

    float acc[2][8][4];
#pragma unroll
    for (int mt = 0; mt < 2; mt++)
#pragma unroll
        for (int nt = 0; nt < 8; nt++)
#pragma unroll
            for (int r = 0; r < 4; r++) acc[mt][nt][r] = 0.f;

    // ldmatrix lane decomposition (same formula for A rows and B n-rows)
    const int mat  = lane >> 3;                     // 0..3
    const int mrow = ((mat & 1) << 3) + (lane & 7); // 0..15
    const int kadd = (mat >> 1) << 3;               // 0 or 8

    gemm_load_stage(smem_u, 0, 0, tid, srcs);
    gemm_load_stage(smem_u, 1, 1, tid, srcs);

    for (int kc = 0; kc < NCHUNK; kc++) {
        if (kc == NCHUNK - 1) { CP_WAIT0(); } else { CP_WAIT1(); }
        __syncthreads();

        const int s = kc & 1;
        const uint32_t aHi = smem_u + s * STAGE_B;
        const uint32_t bHi = aHi + 2 * TILE_B;

#pragma unroll
        for (int ks = 0; ks < 2; ks++) {
            uint32_t ahi[2][4], alo[2][4];
#pragma unroll
            for (int mt = 0; mt < 2; mt++) {
                uint32_t ad = aHi +
                    (uint32_t)((wm + mt * 16 + mrow) * ASTRIDE + ks * 16 + kadd) * 2;
                LDMATRIX_X4(ahi[mt][0], ahi[mt][1], ahi[mt][2], ahi[mt][3], ad);
                ad += TILE_B;   // Alo tile directly after Ahi
                LDMATRIX_X4(alo[mt][0], alo[mt][1], alo[mt][2], alo[mt][3], ad);
            }
            uint32_t bhi[8][2], blo[8][2];
#pragma unroll
            for (int nt2 = 0; nt2 < 4; nt2++) {
                uint32_t bd = bHi +
                    (uint32_t)((wn + nt2 * 16 + mrow) * ASTRIDE + ks * 16 + kadd) * 2;
                uint32_t r0, r1, r2, r3;
                LDMATRIX_X4(r0, r1, r2, r3, bd);
                bhi[2 * nt2][0] = r0; bhi[2 * nt2 + 1][0] = r1;
                bhi[2 * nt2][1] = r2; bhi[2 * nt2 + 1][1] = r3;
                bd += TILE_B;   // Blo tile directly after Bhi
                LDMATRIX_X4(r0, r1, r2, r3, bd);
                blo[2 * nt2][0] = r0; blo[2 * nt2 + 1][0] = r1;
                blo[2 * nt2][1] = r2; blo[2 * nt2 + 1][1] = r3;
            }
#pragma unroll
            for (int mt = 0; mt < 2; mt++)
#pragma unroll
                for (int nt = 0; nt < 8; nt++) {
                    mma_bf16(acc[mt][nt], ahi[mt], bhi[nt]);
                    mma_bf16(acc[mt][nt], ahi[mt], blo[nt]);
                    mma_bf16(acc[mt][nt], alo[mt], bhi[nt]);
                }
        }
        __syncthreads();
        if (kc + 2 < NCHUNK)
            gemm_load_stage(smem_u, s, kc + 2, tid, srcs);
    }

    // ---- epilogue: write C (fragment layout of m16n8, fp32) ----
    const int gid = lane >> 2;     // row group 0..7
    const int tig = lane & 3;      // col pair 0..3
#pragma unroll
    for (int mt = 0; mt < 2; mt++)
#pragma unroll
        for (int nt = 0; nt < 8; nt++) {
            int row = m0 + wm + mt * 16 + gid;
            int col = n0 + wn + nt * 8 + tig * 2;
            float2 lo2 = make_float2(acc[mt][nt][0], acc[mt][nt][1]);
            float2 hi2 = make_float2(acc[mt][nt][2], acc[mt][nt][3]);
            *(float2*)&C[(size_t)row * Ntot + col]       = lo2;
            *(float2*)&C[(size_t)(row + 8) * Ntot + col] = hi2;
        }
}

// ---------------------------------------------------------------------------
// fp32 flash attention with KV-cache (unchanged from R2 passing version)
// ---------------------------------------------------------------------------
#define ATT_BM 64
#define ATT_BN 128
#define PADW   132

#define ATT_SMEM_FLOATS (ATT_BM*PADW + 128*PADW + 128*PADW + ATT_BM*PADW + 3*ATT_BM)
#define ATT_SMEM_BYTES  (ATT_SMEM_FLOATS * sizeof(float))

__global__ __launch_bounds__(256, 1) void attn_kernel(
    const float* __restrict__ past_k, const float* __restrict__ past_v)
{
    extern __shared__ float sm[];
    float* Qs   = sm;
    float* Kt   = Qs + ATT_BM * PADW;
    float* Vs   = Kt + 128 * PADW;
    float* Ss   = Vs + 128 * PADW;
    float* mrow = Ss + ATT_BM * PADW;
    float* lrow = mrow + ATT_BM;
    float* arow = lrow + ATT_BM;

    const int tid = threadIdx.x;
    const int q0  = blockIdx.x * ATT_BM;
    const int h   = blockIdx.y;
    const int b   = blockIdx.z;
    const int kvh = h >> 2;

    if (tid < ATT_BM) { mrow[tid] = -1e30f; lrow[tid] = 0.f; }

    {
        const float* qb = g_q + (size_t)(b * SEQ + q0) * DMODEL + h * HEADD;
#pragma unroll
        for (int i = 0; i < 8; i++) {
            int idx = tid + i * 256;
            int qr = idx >> 5, qc = (idx & 31) << 2;
            *(float4*)&Qs[qr * PADW + qc] =
                *(const float4*)(qb + (size_t)qr * DMODEL + qc);
        }
    }

    const int tx = tid & 15;
    const int ty = tid >> 4;

    float acc[4][8];
#pragma unroll
    for (int i = 0; i < 4; i++)
#pragma unroll
        for (int j = 0; j < 8; j++) acc[i][j] = 0.f;

    const int kmax = PAST + q0 + ATT_BM;

    for (int n0 = 0; n0 < kmax; n0 += ATT_BN) {
        __syncthreads();

#pragma unroll
        for (int i = 0; i < 16; i++) {
            int idx = tid + i * 256;
            int kr = idx >> 5;
            int kc = (idx & 31) << 2;
            int j  = n0 + kr;
            const float *kp, *vp;
            if (j < PAST) {
                size_t off = ((size_t)(b * PAST + j) * NKV + kvh) * HEADD;
                kp = past_k + off;  vp = past_v + off;
            } else {
                size_t off = ((size_t)(b * SEQ + (j - PAST)) * NKV + kvh) * HEADD;
                kp = g_kn + off;    vp = g_vn + off;
            }
            float4 k4 = *(const float4*)(kp + kc);
            Kt[(kc + 0) * PADW + kr] = k4.x;
            Kt[(kc + 1) * PADW + kr] = k4.y;
            Kt[(kc + 2) * PADW + kr] = k4.z;
            Kt[(kc + 3) * PADW + kr] = k4.w;
            *(float4*)&Vs[kr * PADW + kc] = *(const float4*)(vp + kc);
        }
        __syncthreads();

        float sacc[4][8];
#pragma unroll
        for (int i = 0; i < 4; i++)
#pragma unroll
            for (int j = 0; j < 8; j++) sacc[i][j] = 0.f;

#pragma unroll 4
        for (int kk = 0; kk < HEADD; kk++) {
            float a[4];
#pragma unroll
            for (int i = 0; i < 4; i++) a[i] = Qs[(ty * 4 + i) * PADW + kk];
            float bb[8];
            *(float4*)(bb)     = *(const float4*)&Kt[kk * PADW + tx * 8];
            *(float4*)(bb + 4) = *(const float4*)&Kt[kk * PADW + tx * 8 + 4];
#pragma unroll
            for (int i = 0; i < 4; i++)
#pragma unroll
                for (int j = 0; j < 8; j++)
                    sacc[i][j] = fmaf(a[i], bb[j], sacc[i][j]);
        }

        const bool need_mask = (n0 + ATT_BN - 1 > PAST + q0);
        const float sc = 0.088388347648318447f;
#pragma unroll
        for (int i = 0; i < 4; i++) {
            int qrow = ty * 4 + i;
            int lim  = PAST + q0 + qrow;
            float o[8];
#pragma unroll
            for (int j = 0; j < 8; j++) {
                float s = sacc[i][j] * sc;
                if (need_mask && (n0 + tx * 8 + j > lim)) s = -1e30f;
                o[j] = s;
            }
            *(float4*)&Ss[qrow * PADW + tx * 8]     = *(float4*)(o);
            *(float4*)&Ss[qrow * PADW + tx * 8 + 4] = *(float4*)(o + 4);
        }
        __syncthreads();

        {
            int r  = tid >> 2;
            int qd = tid & 3;
            float* srow = Ss + r * PADW + qd * 32;
            float lm = -1e30f;
#pragma unroll
            for (int jj = 0; jj < 32; jj++) lm = fmaxf(lm, srow[jj]);
            lm = fmaxf(lm, __shfl_xor_sync(0xffffffffu, lm, 1));
            lm = fmaxf(lm, __shfl_xor_sync(0xffffffffu, lm, 2));
            float mprev = mrow[r];
            float mnew  = fmaxf(mprev, lm);
            float ls = 0.f;
#pragma unroll
            for (int jj = 0; jj < 32; jj++) {
                float p = __expf(srow[jj] - mnew);
                srow[jj] = p;
                ls += p;
            }
            ls += __shfl_xor_sync(0xffffffffu, ls, 1);
            ls += __shfl_xor_sync(0xffffffffu, ls, 2);
            if (qd == 0) {
                float al = __expf(mprev - mnew);
                mrow[r] = mnew;
                lrow[r] = lrow[r] * al + ls;
                arow[r] = al;
            }
        }
        __syncthreads();

#pragma unroll
        for (int i = 0; i < 4; i++) {
            float al = arow[ty * 4 + i];
#pragma unroll
            for (int j = 0; j < 8; j++) acc[i][j] *= al;
        }
#pragma unroll 4
        for (int j = 0; j < ATT_BN; j++) {
            float vv[8];
            *(float4*)(vv)     = *(const float4*)&Vs[j * PADW + tx * 8];
            *(float4*)(vv + 4) = *(const float4*)&Vs[j * PADW + tx * 8 + 4];
            float p0 = Ss[(ty * 4 + 0) * PADW + j];
            float p1 = Ss[(ty * 4 + 1) * PADW + j];
            float p2 = Ss[(ty * 4 + 2) * PADW + j];
            float p3 = Ss[(ty * 4 + 3) * PADW + j];
#pragma unroll
            for (int c = 0; c < 8; c++) {
                acc[0][c] = fmaf(p0, vv[c], acc[0][c]);
                acc[1][c] = fmaf(p1, vv[c], acc[1][c]);
                acc[2][c] = fmaf(p2, vv[c], acc[2][c]);
                acc[3][c] = fmaf(p3, vv[c], acc[3][c]);
            }
        }
    }

#pragma unroll
    for (int i = 0; i < 4; i++) {
        int qrow = ty * 4 + i;
        float inv = 1.f / lrow[qrow];
        float* op = g_att + (size_t)(b * SEQ + q0 + qrow) * DMODEL + h * HEADD + tx * 8;
        float4 o0 = make_float4(acc[i][0] * inv, acc[i][1] * inv,
                                acc[i][2] * inv, acc[i][3] * inv);
        float4 o1 = make_float4(acc[i][4] * inv, acc[i][5] * inv,
                                acc[i][6] * inv, acc[i][7] * inv);
        *(float4*)op       = o0;
        *(float4*)(op + 4) = o1;
    }
}

// ---------------------------------------------------------------------------
// Launch
// ---------------------------------------------------------------------------
extern "C" void kernel_launch(void* const* d_in, const int* in_sizes, int n_in,
                              void* d_out, int out_size)
{
    const float* x      = (const float*)d_in[0];
    const float* past_k = (const float*)d_in[1];
    const float* past_v = (const float*)d_in[2];
    const float* Wq     = (const float*)d_in[3];
    const float* Wk     = (const float*)d_in[4];
    const float* Wv     = (const float*)d_in[5];
    const float* Wo     = (const float*)d_in[6];
    float* out = (float*)d_out;

    void *pq, *pkn, *pvn, *patt;
    void *pxh, *pxl, *pah, *pal;
    void *pwqh, *pwql, *pwkh, *pwkl, *pwvh, *pwvl, *pwoh, *pwol;
    cudaGetSymbolAddress(&pq,  g_q);
    cudaGetSymbolAddress(&pkn, g_kn);
    cudaGetSymbolAddress(&pvn, g_vn);
    cudaGetSymbolAddress(&patt, g_att);
    cudaGetSymbolAddress(&pxh, g_xhi);
    cudaGetSymbolAddress(&pxl, g_xlo);
    cudaGetSymbolAddress(&pah, g_athi);
    cudaGetSymbolAddress(&pal, g_atlo);
    cudaGetSymbolAddress(&pwqh, g_wqt_hi);
    cudaGetSymbolAddress(&pwql, g_wqt_lo);
    cudaGetSymbolAddress(&pwkh, g_wkt_hi);
    cudaGetSymbolAddress(&pwkl, g_wkt_lo);
    cudaGetSymbolAddress(&pwvh, g_wvt_hi);
    cudaGetSymbolAddress(&pwvl, g_wvt_lo);
    cudaGetSymbolAddress(&pwoh, g_wot_hi);
    cudaGetSymbolAddress(&pwol, g_wot_lo);

    cudaFuncSetAttribute(attn_kernel,
                         cudaFuncAttributeMaxDynamicSharedMemorySize,
                         (int)ATT_SMEM_BYTES);
    cudaFuncSetAttribute(hmma_gemm_kernel,
                         cudaFuncAttributeMaxDynamicSharedMemorySize,
                         (int)GSMEM_B);

    const size_t nx = (size_t)NTOK * DMODEL;
    dim3 blk(256);

    // ---- conversions ----
    split_kernel<<<(unsigned)(nx / (256 * 4)), blk>>>(
        x, (__nv_bfloat16*)pxh, (__nv_bfloat16*)pxl, nx);
    tsplit_kernel<<<dim3(DMODEL / 32, KDIM / 32), blk>>>(
        Wq, (__nv_bfloat16*)pwqh, (__nv_bfloat16*)pwql, KDIM, DMODEL);
    tsplit_kernel<<<dim3((NKV * HEADD) / 32, KDIM / 32), blk>>>(
        Wk, (__nv_bfloat16*)pwkh, (__nv_bfloat16*)pwkl, KDIM, NKV * HEADD);
    tsplit_kernel<<<dim3((NKV * HEADD) / 32, KDIM / 32), blk>>>(
        Wv, (__nv_bfloat16*)pwvh, (__nv_bfloat16*)pwvl, KDIM, NKV * HEADD);
    tsplit_kernel<<<dim3(DMODEL / 32, KDIM / 32), blk>>>(
        Wo, (__nv_bfloat16*)pwoh, (__nv_bfloat16*)pwol, KDIM, DMODEL);

    // ---- QKV projections (HMMA split-bf16) ----
    hmma_gemm_kernel<<<dim3(DMODEL / 128, NTOK / 128), blk, GSMEM_B>>>(
        (const __nv_bfloat16*)pxh, (const __nv_bfloat16*)pxl,
        (const __nv_bfloat16*)pwqh, (const __nv_bfloat16*)pwql,
        (float*)pq, DMODEL);
    hmma_gemm_kernel<<<dim3((NKV * HEADD) / 128, NTOK / 128), blk, GSMEM_B>>>(
        (const __nv_bfloat16*)pxh, (const __nv_bfloat16*)pxl,
        (const __nv_bfloat16*)pwkh, (const __nv_bfloat16*)pwkl,
        (float*)pkn, NKV * HEADD);
    hmma_gemm_kernel<<<dim3((NKV * HEADD) / 128, NTOK / 128), blk, GSMEM_B>>>(
        (const __nv_bfloat16*)pxh, (const __nv_bfloat16*)pxl,
        (const __nv_bfloat16*)pwvh, (const __nv_bfloat16*)pwvl,
        (float*)pvn, NKV * HEADD);

    // ---- flash attention (fp32) ----
    attn_kernel<<<dim3(SEQ / ATT_BM, NHEADS, BATCH), blk, ATT_SMEM_BYTES>>>(
        past_k, past_v);

    // ---- O projection ----
    split_kernel<<<(unsigned)(nx / (256 * 4)), blk>>>(
        (const float*)patt, (__nv_bfloat16*)pah, (__nv_bfloat16*)pal, nx);
    hmma_gemm_kernel<<<dim3(DMODEL / 128, NTOK / 128), blk, GSMEM_B>>>(
        (const __nv_bfloat16*)pah, (const __nv_bfloat16*)pal,
        (const __nv_bfloat16*)pwoh, (const __nv_bfloat16*)pwol,
        out, DMODEL);
}

// round 6
// speedup vs baseline: 3.1986x; 2.0259x over previous
#include <cuda_runtime.h>
#include <cuda_bf16.h>
#include <cstdint>

// ---------------------------------------------------------------------------
// Problem constants
// ---------------------------------------------------------------------------
#define BATCH 2
#define SEQ   2048
#define DMODEL 4096
#define NHEADS 32
#define NKV    8
#define HEADD  128
#define GRP    4
#define PAST   1024
#define TTOT   3072
#define NTOK   (BATCH * SEQ)   // 4096
#define KDIM   DMODEL

// ---------------------------------------------------------------------------
// Scratch buffers (device globals: no cudaMalloc allowed)
// ---------------------------------------------------------------------------
__device__ __nv_bfloat16 g_xhi[(size_t)NTOK * DMODEL];
__device__ __nv_bfloat16 g_xlo[(size_t)NTOK * DMODEL];
__device__ __nv_bfloat16 g_qhi[(size_t)NTOK * DMODEL];
__device__ __nv_bfloat16 g_qlo[(size_t)NTOK * DMODEL];
__device__ __nv_bfloat16 g_athi[(size_t)NTOK * DMODEL];
__device__ __nv_bfloat16 g_atlo[(size_t)NTOK * DMODEL];
// unified KV cache [B][KV][TTOT][HD], bf16 hi/lo
__device__ __nv_bfloat16 g_kch[(size_t)BATCH * NKV * TTOT * HEADD];
__device__ __nv_bfloat16 g_kcl[(size_t)BATCH * NKV * TTOT * HEADD];
__device__ __nv_bfloat16 g_vch[(size_t)BATCH * NKV * TTOT * HEADD];
__device__ __nv_bfloat16 g_vcl[(size_t)BATCH * NKV * TTOT * HEADD];
// transposed split weights [N][K]
__device__ __nv_bfloat16 g_wqt_hi[(size_t)DMODEL * KDIM];
__device__ __nv_bfloat16 g_wqt_lo[(size_t)DMODEL * KDIM];
__device__ __nv_bfloat16 g_wkt_hi[(size_t)(NKV*HEADD) * KDIM];
__device__ __nv_bfloat16 g_wkt_lo[(size_t)(NKV*HEADD) * KDIM];
__device__ __nv_bfloat16 g_wvt_hi[(size_t)(NKV*HEADD) * KDIM];
__device__ __nv_bfloat16 g_wvt_lo[(size_t)(NKV*HEADD) * KDIM];
__device__ __nv_bfloat16 g_wot_hi[(size_t)DMODEL * KDIM];
__device__ __nv_bfloat16 g_wot_lo[(size_t)DMODEL * KDIM];

// ---------------------------------------------------------------------------
// PTX helpers (baseline sm_80+ only — tcgen05 is rejected by this toolchain)
// ---------------------------------------------------------------------------
__device__ __forceinline__ uint32_t smem_to_u32(const void* p) {
    uint32_t a;
    asm("{ .reg .u64 t; cvta.to.shared.u64 t, %1; cvt.u32.u64 %0, t; }"
        : "=r"(a) : "l"(p));
    return a;
}
#define CP_ASYNC16(dst, src) \
    asm volatile("cp.async.ca.shared.global [%0], [%1], 16;" \
        :: "r"(dst), "l"(src))
#define CP_COMMIT() asm volatile("cp.async.commit_group;")
#define CP_WAIT1()  asm volatile("cp.async.wait_group 1;")
#define CP_WAIT0()  asm volatile("cp.async.wait_group 0;")

#define LDMATRIX_X4(r0, r1, r2, r3, addr) \
    asm volatile("ldmatrix.sync.aligned.m8n8.x4.shared.b16 {%0,%1,%2,%3}, [%4];" \
        : "=r"(r0), "=r"(r1), "=r"(r2), "=r"(r3) : "r"(addr))
#define LDMATRIX_X4_T(r0, r1, r2, r3, addr) \
    asm volatile("ldmatrix.sync.aligned.m8n8.x4.trans.shared.b16 {%0,%1,%2,%3}, [%4];" \
        : "=r"(r0), "=r"(r1), "=r"(r2), "=r"(r3) : "r"(addr))

__device__ __forceinline__ void mma_bf16(float* c, const uint32_t* a,
                                         const uint32_t* b) {
    asm volatile(
        "mma.sync.aligned.m16n8k16.row.col.f32.bf16.bf16.f32 "
        "{%0,%1,%2,%3}, {%4,%5,%6,%7}, {%8,%9}, {%0,%1,%2,%3};"
        : "+f"(c[0]), "+f"(c[1]), "+f"(c[2]), "+f"(c[3])
        : "r"(a[0]), "r"(a[1]), "r"(a[2]), "r"(a[3]), "r"(b[0]), "r"(b[1]));
}

// pack 2 floats -> bf16x2 (p0 low half) plus residual bf16x2
__device__ __forceinline__ void split_pack(float p0, float p1,
                                           uint32_t& hi, uint32_t& lo) {
    uint32_t h;
    asm("cvt.rn.bf16x2.f32 %0, %1, %2;" : "=r"(h) : "f"(p1), "f"(p0));
    float h0 = __uint_as_float(h << 16);
    float h1 = __uint_as_float(h & 0xffff0000u);
    uint32_t l;
    asm("cvt.rn.bf16x2.f32 %0, %1, %2;" : "=r"(l) : "f"(p1 - h1), "f"(p0 - h0));
    hi = h; lo = l;
}

__device__ __forceinline__ void split_store2(
    __nv_bfloat16* __restrict__ hi, __nv_bfloat16* __restrict__ lo,
    size_t off, float a, float b) {
    uint32_t h, l;
    split_pack(a, b, h, l);
    *(uint32_t*)(hi + off) = h;
    *(uint32_t*)(lo + off) = l;
}

// ---------------------------------------------------------------------------
// fp32 -> bf16 hi/lo split (x at entry)
// ---------------------------------------------------------------------------
__global__ __launch_bounds__(256) void split_kernel(
    const float* __restrict__ src, __nv_bfloat16* __restrict__ hi,
    __nv_bfloat16* __restrict__ lo, size_t n)
{
    size_t i = ((size_t)blockIdx.x * 256 + threadIdx.x) * 4;
    if (i >= n) return;
    float4 v = *(const float4*)(src + i);
    split_store2(hi, lo, i,     v.x, v.y);
    split_store2(hi, lo, i + 2, v.z, v.w);
}

// ---------------------------------------------------------------------------
// Transpose + split: W[K][N] fp32 -> Wt_hi/lo[N][K] bf16
// ---------------------------------------------------------------------------
__global__ __launch_bounds__(256) void tsplit_kernel(
    const float* __restrict__ W, __nv_bfloat16* __restrict__ thi,
    __nv_bfloat16* __restrict__ tlo, int Kd, int Nd)
{
    __shared__ float t[32][33];
    int tx = threadIdx.x & 31;
    int ty = threadIdx.x >> 5;
    int n_base = blockIdx.x * 32;
    int k_base = blockIdx.y * 32;
#pragma unroll
    for (int j = 0; j < 32; j += 8)
        t[ty + j][tx] = W[(size_t)(k_base + ty + j) * Nd + n_base + tx];
    __syncthreads();
#pragma unroll
    for (int j = 0; j < 32; j += 8) {
        int n = n_base + ty + j;
        int k = k_base + tx;
        float v = t[tx][ty + j];
        __nv_bfloat16 h = __float2bfloat16(v);
        thi[(size_t)n * Kd + k] = h;
        tlo[(size_t)n * Kd + k] = __float2bfloat16(v - __bfloat162float(h));
    }
}

// ---------------------------------------------------------------------------
// past_k/past_v [B][P][KV][HD] fp32 -> unified cache [B][KV][t][HD] bf16 hi/lo
// ---------------------------------------------------------------------------
__global__ __launch_bounds__(256) void past_split_kernel(
    const float* __restrict__ pk, const float* __restrict__ pv)
{
    size_t idx = ((size_t)blockIdx.x * 256 + threadIdx.x) * 4;
    int d  = (int)(idx & 127);
    int kv = (int)((idx >> 7) & 7);
    int p  = (int)((idx >> 10) & 1023);
    int b  = (int)(idx >> 20);
    size_t dst = (((size_t)b * NKV + kv) * TTOT + p) * HEADD + d;
    float4 a = *(const float4*)(pk + idx);
    split_store2(g_kch, g_kcl, dst,     a.x, a.y);
    split_store2(g_kch, g_kcl, dst + 2, a.z, a.w);
    float4 c = *(const float4*)(pv + idx);
    split_store2(g_vch, g_vcl, dst,     c.x, c.y);
    split_store2(g_vch, g_vcl, dst + 2, c.z, c.w);
}

// ---------------------------------------------------------------------------
// HMMA split GEMM with templated epilogue:
//   MODE 0: C fp32 row-major
//   MODE 1: split bf16 hi/lo row-major (Q projection / attn input)
//   MODE 2: split bf16 hi/lo into unified KV cache layout
// ---------------------------------------------------------------------------
#define BK       32
#define ASTRIDE  40
#define TILE_B   (128 * ASTRIDE * 2)
#define STAGE_B  (4 * TILE_B)
#define GSMEM_B  (2 * STAGE_B)
#define NCHUNK   (KDIM / BK)

__device__ __forceinline__ void gemm_load_stage(
    uint32_t smem_u, int stage, int kc, int tid,
    const __nv_bfloat16* const* srcs)
{
#pragma unroll
    for (int t = 0; t < 4; t++) {
        uint32_t dbase = smem_u + stage * STAGE_B + t * TILE_B;
        const __nv_bfloat16* sb = srcs[t] + kc * BK;
#pragma unroll
        for (int i = 0; i < 2; i++) {
            int slot = tid + i * 256;
            int r = slot >> 2;
            int c = slot & 3;
            uint32_t dst = dbase + (uint32_t)(r * ASTRIDE + c * 8) * 2;
            CP_ASYNC16(dst, sb + (size_t)r * KDIM + c * 8);
        }
    }
    CP_COMMIT();
}

template<int MODE>
__global__ __launch_bounds__(256, 1) void hmma_gemm_kernel(
    const __nv_bfloat16* __restrict__ Ahi, const __nv_bfloat16* __restrict__ Alo,
    const __nv_bfloat16* __restrict__ Bhi, const __nv_bfloat16* __restrict__ Blo,
    float* __restrict__ C, __nv_bfloat16* __restrict__ Chi,
    __nv_bfloat16* __restrict__ Clo, int Ntot)
{
    extern __shared__ char smem[];
    const uint32_t smem_u = smem_to_u32(smem);
    const int tid  = threadIdx.x;
    const int lane = tid & 31;
    const int wid  = tid >> 5;
    const int wm   = (wid >> 1) * 32;
    const int wn   = (wid & 1) * 64;
    const int m0   = blockIdx.y * 128;
    const int n0   = blockIdx.x * 128;

    const __nv_bfloat16* srcs[4] = {
        Ahi + (size_t)m0 * KDIM, Alo + (size_t)m0 * KDIM,
        Bhi + (size_t)n0 * KDIM, Blo + (size_t)n0 * KDIM };

    float acc[2][8][4];
#pragma unroll
    for (int mt = 0; mt < 2; mt++)
#pragma unroll
        for (int nt = 0; nt < 8; nt++)
#pragma unroll
            for (int r = 0; r < 4; r++) acc[mt][nt][r] = 0.f;

    const int mat  = lane >> 3;
    const int mrow = ((mat & 1) << 3) + (lane & 7);
    const int kadd = (mat >> 1) << 3;

    gemm_load_stage(smem_u, 0, 0, tid, srcs);
    gemm_load_stage(smem_u, 1, 1, tid, srcs);

    for (int kc = 0; kc < NCHUNK; kc++) {
        if (kc == NCHUNK - 1) { CP_WAIT0(); } else { CP_WAIT1(); }
        __syncthreads();

        const int s = kc & 1;
        const uint32_t aHi = smem_u + s * STAGE_B;
        const uint32_t bHi = aHi + 2 * TILE_B;

#pragma unroll
        for (int ks = 0; ks < 2; ks++) {
            uint32_t ahi[2][4], alo[2][4];
#pragma unroll
            for (int mt = 0; mt < 2; mt++) {
                uint32_t ad = aHi +
                    (uint32_t)((wm + mt * 16 + mrow) * ASTRIDE + ks * 16 + kadd) * 2;
                LDMATRIX_X4(ahi[mt][0], ahi[mt][1], ahi[mt][2], ahi[mt][3], ad);
                ad += TILE_B;
                LDMATRIX_X4(alo[mt][0], alo[mt][1], alo[mt][2], alo[mt][3], ad);
            }
            uint32_t bhi[8][2], blo[8][2];
#pragma unroll
            for (int nt2 = 0; nt2 < 4; nt2++) {
                uint32_t bd = bHi +
                    (uint32_t)((wn + nt2 * 16 + mrow) * ASTRIDE + ks * 16 + kadd) * 2;
                uint32_t r0, r1, r2, r3;
                LDMATRIX_X4(r0, r1, r2, r3, bd);
                bhi[2 * nt2][0] = r0; bhi[2 * nt2 + 1][0] = r1;
                bhi[2 * nt2][1] = r2; bhi[2 * nt2 + 1][1] = r3;
                bd += TILE_B;
                LDMATRIX_X4(r0, r1, r2, r3, bd);
                blo[2 * nt2][0] = r0; blo[2 * nt2 + 1][0] = r1;
                blo[2 * nt2][1] = r2; blo[2 * nt2 + 1][1] = r3;
            }
#pragma unroll
            for (int mt = 0; mt < 2; mt++)
#pragma unroll
                for (int nt = 0; nt < 8; nt++) {
                    mma_bf16(acc[mt][nt], ahi[mt], bhi[nt]);
                    mma_bf16(acc[mt][nt], ahi[mt], blo[nt]);
                    mma_bf16(acc[mt][nt], alo[mt], bhi[nt]);
                }
        }
        __syncthreads();
        if (kc + 2 < NCHUNK)
            gemm_load_stage(smem_u, s, kc + 2, tid, srcs);
    }

    const int gid = lane >> 2;
    const int tig = lane & 3;
#pragma unroll
    for (int mt = 0; mt < 2; mt++)
#pragma unroll
        for (int nt = 0; nt < 8; nt++) {
            int row = m0 + wm + mt * 16 + gid;
            int col = n0 + wn + nt * 8 + tig * 2;
            if (MODE == 0) {
                *(float2*)&C[(size_t)row * Ntot + col] =
                    make_float2(acc[mt][nt][0], acc[mt][nt][1]);
                *(float2*)&C[(size_t)(row + 8) * Ntot + col] =
                    make_float2(acc[mt][nt][2], acc[mt][nt][3]);
            } else if (MODE == 1) {
                split_store2(Chi, Clo, (size_t)row * Ntot + col,
                             acc[mt][nt][0], acc[mt][nt][1]);
                split_store2(Chi, Clo, (size_t)(row + 8) * Ntot + col,
                             acc[mt][nt][2], acc[mt][nt][3]);
            } else {
                int kvh = col >> 7, d = col & 127;
#pragma unroll
                for (int rr = 0; rr < 2; rr++) {
                    int r = row + rr * 8;
                    int bb = r >> 11, ss = r & 2047;
                    size_t off = (((size_t)bb * NKV + kvh) * TTOT + PAST + ss)
                                 * HEADD + d;
                    split_store2(Chi, Clo, off,
                                 acc[mt][nt][rr * 2], acc[mt][nt][rr * 2 + 1]);
                }
            }
        }
}

// ---------------------------------------------------------------------------
// HMMA split-bf16 flash attention.
// BM=128 (8 warps x m16), BN=64 keys/iter, HD=128. Q in smem (loaded once),
// K/V hi/lo tiles cp.async double-buffered. Softmax in fragment registers.
// ---------------------------------------------------------------------------
#define FA_BM   128
#define FA_BN   64
#define FA_STR  136                         // bf16 row stride (272 B)
#define FA_QTILE (FA_BM * FA_STR * 2)       // 34,816 B
#define FA_KTILE (FA_BN * FA_STR * 2)       // 17,408 B
#define FA_STAGE (4 * FA_KTILE)             // 69,632 B (Khi,Klo,Vhi,Vlo)
#define FA_KV_OFF (2 * FA_QTILE)            // 69,632
#define FA_SMEM  (FA_KV_OFF + 2 * FA_STAGE) // 208,896 B

__global__ __launch_bounds__(256, 1) void fa_kernel(
    const __nv_bfloat16* __restrict__ qhi, const __nv_bfloat16* __restrict__ qlo,
    __nv_bfloat16* __restrict__ athi, __nv_bfloat16* __restrict__ atlo)
{
    extern __shared__ char smem[];
    const uint32_t su = smem_to_u32(smem);
    const int tid = threadIdx.x, lane = tid & 31, wid = tid >> 5;
    const int q0 = blockIdx.x * FA_BM;
    const int h = blockIdx.y, b = blockIdx.z, kvh = h >> 2;

    const size_t kvbase = ((size_t)b * NKV + kvh) * TTOT * HEADD;
    const __nv_bfloat16* kH = g_kch + kvbase;
    const __nv_bfloat16* kL = g_kcl + kvbase;
    const __nv_bfloat16* vH = g_vch + kvbase;
    const __nv_bfloat16* vL = g_vcl + kvbase;

    // ---- Q tiles hi/lo -> smem (group 0 with first KV stage) ----
    {
        const size_t qoff = (size_t)(b * SEQ + q0) * DMODEL + h * HEADD;
        const __nv_bfloat16* sh = qhi + qoff;
        const __nv_bfloat16* sl = qlo + qoff;
#pragma unroll
        for (int i = 0; i < 8; i++) {
            int slot = tid + i * 256;          // 0..2047
            int r = slot >> 4, c = slot & 15;
            uint32_t d0 = su + (uint32_t)(r * FA_STR + c * 8) * 2;
            CP_ASYNC16(d0, sh + (size_t)r * DMODEL + c * 8);
            CP_ASYNC16(d0 + FA_QTILE, sl + (size_t)r * DMODEL + c * 8);
        }
    }
    auto load_kv = [&](int stage, int t) {
        uint32_t base = su + FA_KV_OFF + stage * FA_STAGE;
        int n0 = t * FA_BN;
#pragma unroll
        for (int i = 0; i < 4; i++) {
            int slot = tid + i * 256;          // 0..1023
            int r = slot >> 4, c = slot & 15;
            uint32_t doff = (uint32_t)(r * FA_STR + c * 8) * 2;
            size_t soff = (size_t)(n0 + r) * HEADD + c * 8;
            CP_ASYNC16(base + doff,                kH + soff);
            CP_ASYNC16(base + FA_KTILE + doff,     kL + soff);
            CP_ASYNC16(base + 2 * FA_KTILE + doff, vH + soff);
            CP_ASYNC16(base + 3 * FA_KTILE + doff, vL + soff);
        }
    };
    const int ntiles = (PAST + q0 + FA_BM) / FA_BN;
    load_kv(0, 0); CP_COMMIT();
    load_kv(1, 1); CP_COMMIT();

    const int gid = lane >> 2, tig = lane & 3;
    const int mat = lane >> 3;
    const int mrow = ((mat & 1) << 3) + (lane & 7);
    const int kadd = (mat >> 1) << 3;
    const int wm = wid * 16;
    const int lim0 = PAST + q0 + wm + gid;     // allowed: col <= lim
    const int lim1 = lim0 + 8;

    float m0 = -1e30f, m1 = -1e30f, l0 = 0.f, l1 = 0.f;
    float oacc[16][4];
#pragma unroll
    for (int i = 0; i < 16; i++)
#pragma unroll
        for (int r = 0; r < 4; r++) oacc[i][r] = 0.f;

    const int vrow = ((mat & 1) << 3) + (lane & 7);

    for (int t = 0; t < ntiles; t++) {
        if (t == ntiles - 1) { CP_WAIT0(); } else { CP_WAIT1(); }
        __syncthreads();
        const uint32_t sk = su + FA_KV_OFF + (t & 1) * FA_STAGE;
        const int n0 = t * FA_BN;

        // ---- S = Q K^T (3-pass split) ----
        float sacc[8][4];
#pragma unroll
        for (int j = 0; j < 8; j++)
#pragma unroll
            for (int r = 0; r < 4; r++) sacc[j][r] = 0.f;

#pragma unroll
        for (int ks = 0; ks < 8; ks++) {
            uint32_t ah[4], al[4];
            uint32_t ad = su + (uint32_t)((wm + mrow) * FA_STR + ks * 16 + kadd) * 2;
            LDMATRIX_X4(ah[0], ah[1], ah[2], ah[3], ad);
            LDMATRIX_X4(al[0], al[1], al[2], al[3], ad + FA_QTILE);
#pragma unroll
            for (int nt2 = 0; nt2 < 4; nt2++) {
                uint32_t bd = sk +
                    (uint32_t)((nt2 * 16 + mrow) * FA_STR + ks * 16 + kadd) * 2;
                uint32_t h0, h1, h2, h3, e0, e1, e2, e3;
                LDMATRIX_X4(h0, h1, h2, h3, bd);
                LDMATRIX_X4(e0, e1, e2, e3, bd + FA_KTILE);
                uint32_t bh0[2] = {h0, h2}, bh1[2] = {h1, h3};
                uint32_t bl0[2] = {e0, e2}, bl1[2] = {e1, e3};
                mma_bf16(sacc[2 * nt2], ah, bh0);
                mma_bf16(sacc[2 * nt2], ah, bl0);
                mma_bf16(sacc[2 * nt2], al, bh0);
                mma_bf16(sacc[2 * nt2 + 1], ah, bh1);
                mma_bf16(sacc[2 * nt2 + 1], ah, bl1);
                mma_bf16(sacc[2 * nt2 + 1], al, bh1);
            }
        }

        // ---- scale + causal mask + tile max ----
        const float sc = 0.088388347648318447f;
        float tm0 = -1e30f, tm1 = -1e30f;
#pragma unroll
        for (int j = 0; j < 8; j++) {
            int c0 = n0 + j * 8 + tig * 2;
            float s0 = sacc[j][0] * sc; if (c0     > lim0) s0 = -1e30f;
            float s1 = sacc[j][1] * sc; if (c0 + 1 > lim0) s1 = -1e30f;
            float s2 = sacc[j][2] * sc; if (c0     > lim1) s2 = -1e30f;
            float s3 = sacc[j][3] * sc; if (c0 + 1 > lim1) s3 = -1e30f;
            sacc[j][0] = s0; sacc[j][1] = s1; sacc[j][2] = s2; sacc[j][3] = s3;
            tm0 = fmaxf(tm0, fmaxf(s0, s1));
            tm1 = fmaxf(tm1, fmaxf(s2, s3));
        }
        tm0 = fmaxf(tm0, __shfl_xor_sync(0xffffffffu, tm0, 1));
        tm0 = fmaxf(tm0, __shfl_xor_sync(0xffffffffu, tm0, 2));
        tm1 = fmaxf(tm1, __shfl_xor_sync(0xffffffffu, tm1, 1));
        tm1 = fmaxf(tm1, __shfl_xor_sync(0xffffffffu, tm1, 2));

        float mn0 = fmaxf(m0, tm0), mn1 = fmaxf(m1, tm1);
        float al0 = __expf(m0 - mn0), al1 = __expf(m1 - mn1);
        m0 = mn0; m1 = mn1;
#pragma unroll
        for (int i = 0; i < 16; i++) {
            oacc[i][0] *= al0; oacc[i][1] *= al0;
            oacc[i][2] *= al1; oacc[i][3] *= al1;
        }

        // ---- P = exp(S - m), row sums ----
        float rs0 = 0.f, rs1 = 0.f;
#pragma unroll
        for (int j = 0; j < 8; j++) {
            float p0 = __expf(sacc[j][0] - mn0);
            float p1 = __expf(sacc[j][1] - mn0);
            float p2 = __expf(sacc[j][2] - mn1);
            float p3 = __expf(sacc[j][3] - mn1);
            sacc[j][0] = p0; sacc[j][1] = p1; sacc[j][2] = p2; sacc[j][3] = p3;
            rs0 += p0 + p1; rs1 += p2 + p3;
        }
        rs0 += __shfl_xor_sync(0xffffffffu, rs0, 1);
        rs0 += __shfl_xor_sync(0xffffffffu, rs0, 2);
        rs1 += __shfl_xor_sync(0xffffffffu, rs1, 1);
        rs1 += __shfl_xor_sync(0xffffffffu, rs1, 2);
        l0 = l0 * al0 + rs0;
        l1 = l1 * al1 + rs1;

        // ---- O += P V (3-pass split), V via trans ldmatrix ----
#pragma unroll
        for (int tk = 0; tk < 4; tk++) {
            uint32_t ph[4], pl[4];
            split_pack(sacc[2 * tk][0],     sacc[2 * tk][1],     ph[0], pl[0]);
            split_pack(sacc[2 * tk][2],     sacc[2 * tk][3],     ph[1], pl[1]);
            split_pack(sacc[2 * tk + 1][0], sacc[2 * tk + 1][1], ph[2], pl[2]);
            split_pack(sacc[2 * tk + 1][2], sacc[2 * tk + 1][3], ph[3], pl[3]);
#pragma unroll
            for (int dt2 = 0; dt2 < 8; dt2++) {
                uint32_t vd = sk + 2 * FA_KTILE +
                    (uint32_t)((tk * 16 + vrow) * FA_STR + dt2 * 16 + kadd) * 2;
                uint32_t r0, r1, r2, r3, s0, s1, s2, s3;
                LDMATRIX_X4_T(r0, r1, r2, r3, vd);               // V hi
                LDMATRIX_X4_T(s0, s1, s2, s3, vd + FA_KTILE);    // V lo
                uint32_t bh0[2] = {r0, r1}, bh1[2] = {r2, r3};
                uint32_t bl0[2] = {s0, s1}, bl1[2] = {s2, s3};
                mma_bf16(oacc[2 * dt2], ph, bh0);
                mma_bf16(oacc[2 * dt2], ph, bl0);
                mma_bf16(oacc[2 * dt2], pl, bh0);
                mma_bf16(oacc[2 * dt2 + 1], ph, bh1);
                mma_bf16(oacc[2 * dt2 + 1], ph, bl1);
                mma_bf16(oacc[2 * dt2 + 1], pl, bh1);
            }
        }
        __syncthreads();
        if (t + 2 < ntiles) { load_kv(t & 1, t + 2); }
    }

    // ---- epilogue: normalize, split-write attn output ----
    float inv0 = 1.f / l0, inv1 = 1.f / l1;
    size_t tok0 = (size_t)(b * SEQ + q0 + wm + gid);
    size_t base0 = tok0 * DMODEL + h * HEADD;
    size_t base1 = base0 + (size_t)8 * DMODEL;
#pragma unroll
    for (int i = 0; i < 16; i++) {
        int d0 = i * 8 + tig * 2;
        split_store2(athi, atlo, base0 + d0, oacc[i][0] * inv0, oacc[i][1] * inv0);
        split_store2(athi, atlo, base1 + d0, oacc[i][2] * inv1, oacc[i][3] * inv1);
    }
}

// ---------------------------------------------------------------------------
// Launch
// ---------------------------------------------------------------------------
extern "C" void kernel_launch(void* const* d_in, const int* in_sizes, int n_in,
                              void* d_out, int out_size)
{
    const float* x      = (const float*)d_in[0];
    const float* past_k = (const float*)d_in[1];
    const float* past_v = (const float*)d_in[2];
    const float* Wq     = (const float*)d_in[3];
    const float* Wk     = (const float*)d_in[4];
    const float* Wv     = (const float*)d_in[5];
    const float* Wo     = (const float*)d_in[6];
    float* out = (float*)d_out;

    void *pxh, *pxl, *pqh, *pql, *pah, *pal;
    void *pkch, *pkcl, *pvch, *pvcl;
    void *pwqh, *pwql, *pwkh, *pwkl, *pwvh, *pwvl, *pwoh, *pwol;
    cudaGetSymbolAddress(&pxh, g_xhi);   cudaGetSymbolAddress(&pxl, g_xlo);
    cudaGetSymbolAddress(&pqh, g_qhi);   cudaGetSymbolAddress(&pql, g_qlo);
    cudaGetSymbolAddress(&pah, g_athi);  cudaGetSymbolAddress(&pal, g_atlo);
    cudaGetSymbolAddress(&pkch, g_kch);  cudaGetSymbolAddress(&pkcl, g_kcl);
    cudaGetSymbolAddress(&pvch, g_vch);  cudaGetSymbolAddress(&pvcl, g_vcl);
    cudaGetSymbolAddress(&pwqh, g_wqt_hi); cudaGetSymbolAddress(&pwql, g_wqt_lo);
    cudaGetSymbolAddress(&pwkh, g_wkt_hi); cudaGetSymbolAddress(&pwkl, g_wkt_lo);
    cudaGetSymbolAddress(&pwvh, g_wvt_hi); cudaGetSymbolAddress(&pwvl, g_wvt_lo);
    cudaGetSymbolAddress(&pwoh, g_wot_hi); cudaGetSymbolAddress(&pwol, g_wot_lo);

    cudaFuncSetAttribute(hmma_gemm_kernel<0>,
        cudaFuncAttributeMaxDynamicSharedMemorySize, (int)GSMEM_B);
    cudaFuncSetAttribute(hmma_gemm_kernel<1>,
        cudaFuncAttributeMaxDynamicSharedMemorySize, (int)GSMEM_B);
    cudaFuncSetAttribute(hmma_gemm_kernel<2>,
        cudaFuncAttributeMaxDynamicSharedMemorySize, (int)GSMEM_B);
    cudaFuncSetAttribute(fa_kernel,
        cudaFuncAttributeMaxDynamicSharedMemorySize, (int)FA_SMEM);

    const size_t nx = (size_t)NTOK * DMODEL;
    dim3 blk(256);

    // ---- conversions ----
    split_kernel<<<(unsigned)(nx / (256 * 4)), blk>>>(
        x, (__nv_bfloat16*)pxh, (__nv_bfloat16*)pxl, nx);
    tsplit_kernel<<<dim3(DMODEL / 32, KDIM / 32), blk>>>(
        Wq, (__nv_bfloat16*)pwqh, (__nv_bfloat16*)pwql, KDIM, DMODEL);
    tsplit_kernel<<<dim3((NKV * HEADD) / 32, KDIM / 32), blk>>>(
        Wk, (__nv_bfloat16*)pwkh, (__nv_bfloat16*)pwkl, KDIM, NKV * HEADD);
    tsplit_kernel<<<dim3((NKV * HEADD) / 32, KDIM / 32), blk>>>(
        Wv, (__nv_bfloat16*)pwvh, (__nv_bfloat16*)pwvl, KDIM, NKV * HEADD);
    tsplit_kernel<<<dim3(DMODEL / 32, KDIM / 32), blk>>>(
        Wo, (__nv_bfloat16*)pwoh, (__nv_bfloat16*)pwol, KDIM, DMODEL);
    past_split_kernel<<<2048, blk>>>(past_k, past_v);

    // ---- projections (HMMA split-bf16, fused split epilogues) ----
    hmma_gemm_kernel<1><<<dim3(DMODEL / 128, NTOK / 128), blk, GSMEM_B>>>(
        (const __nv_bfloat16*)pxh, (const __nv_bfloat16*)pxl,
        (const __nv_bfloat16*)pwqh, (const __nv_bfloat16*)pwql,
        nullptr, (__nv_bfloat16*)pqh, (__nv_bfloat16*)pql, DMODEL);
    hmma_gemm_kernel<2><<<dim3((NKV * HEADD) / 128, NTOK / 128), blk, GSMEM_B>>>(
        (const __nv_bfloat16*)pxh, (const __nv_bfloat16*)pxl,
        (const __nv_bfloat16*)pwkh, (const __nv_bfloat16*)pwkl,
        nullptr, (__nv_bfloat16*)pkch, (__nv_bfloat16*)pkcl, NKV * HEADD);
    hmma_gemm_kernel<2><<<dim3((NKV * HEADD) / 128, NTOK / 128), blk, GSMEM_B>>>(
        (const __nv_bfloat16*)pxh, (const __nv_bfloat16*)pxl,
        (const __nv_bfloat16*)pwvh, (const __nv_bfloat16*)pwvl,
        nullptr, (__nv_bfloat16*)pvch, (__nv_bfloat16*)pvcl, NKV * HEADD);

    // ---- flash attention (HMMA split-bf16) ----
    fa_kernel<<<dim3(SEQ / FA_BM, NHEADS, BATCH), blk, FA_SMEM>>>(
        (const __nv_bfloat16*)pqh, (const __nv_bfloat16*)pql,
        (__nv_bfloat16*)pah, (__nv_bfloat16*)pal);

    // ---- O projection -> d_out ----
    hmma_gemm_kernel<0><<<dim3(DMODEL / 128, NTOK / 128), blk, GSMEM_B>>>(
        (const __nv_bfloat16*)pah, (const __nv_bfloat16*)pal,
        (const __nv_bfloat16*)pwoh, (const __nv_bfloat16*)pwol,
        out, nullptr, nullptr, DMODEL);
}